// round 11
// baseline (speedup 1.0000x reference)
#include <cuda_runtime.h>
#include <cuda_bf16.h>
#include <cstdint>

// Problem constants
#define NN   64
#define LL   1024
#define DD   512
#define LI_  1022
#define SS   127
#define OUTC 300
#define EPSF 1e-5f
#define MR   8128          // NN*SS = 127*64 exactly

#define KT2  1024          // g_B row: [Bh(512) | Bl(512)]
#define NCHK 8             // 8 K-chunks of 64

// Global scratch (allocation-free rule)
__device__ __align__(128) __nv_bfloat16 g_B[(size_t)320 * KT2];

__device__ __forceinline__ uint32_t smem_u32(const void* p) {
    return (uint32_t)__cvta_generic_to_shared(p);
}
__device__ __forceinline__ void ldsm_x4(uint32_t addr, uint32_t& r0, uint32_t& r1,
                                        uint32_t& r2, uint32_t& r3) {
    asm volatile("ldmatrix.sync.aligned.m8n8.x4.shared.b16 {%0,%1,%2,%3}, [%4];"
                 : "=r"(r0), "=r"(r1), "=r"(r2), "=r"(r3) : "r"(addr));
}
__device__ __forceinline__ void ldsm_x2(uint32_t addr, uint32_t& r0, uint32_t& r1) {
    asm volatile("ldmatrix.sync.aligned.m8n8.x2.shared.b16 {%0,%1}, [%2];"
                 : "=r"(r0), "=r"(r1) : "r"(addr));
}
__device__ __forceinline__ void mma16816(float* c, const uint32_t* a,
                                         uint32_t b0, uint32_t b1) {
    asm volatile("mma.sync.aligned.m16n8k16.row.col.f32.bf16.bf16.f32 "
                 "{%0,%1,%2,%3}, {%4,%5,%6,%7}, {%8,%9}, {%0,%1,%2,%3};"
                 : "+f"(c[0]), "+f"(c[1]), "+f"(c[2]), "+f"(c[3])
                 : "r"(a[0]), "r"(a[1]), "r"(a[2]), "r"(a[3]), "r"(b0), "r"(b1));
}
__device__ __forceinline__ void cp_async16(uint32_t dst, const void* src) {
    asm volatile("cp.async.cg.shared.global [%0], [%1], 16;" :: "r"(dst), "l"(src));
}
#define CP_COMMIT() asm volatile("cp.async.commit_group;")
#define CP_WAIT2()  asm volatile("cp.async.wait_group 2;" ::: "memory")

__device__ __forceinline__ uint32_t pack_bf2(float a, float b) {
    __nv_bfloat162 p = __float22bfloat162_rn(make_float2(a, b));
    return *(uint32_t*)&p;
}

// ---------------------------------------------------------------------------
// Kernel 1: W split -> g_B [Bh|Bl] (rows>=300 zero)  +  use = t1[:,0,:] copy.
// grid = 384: b<320 W rows; b>=320 use rows. 128 threads.
// ---------------------------------------------------------------------------
__global__ void prep_kernel(const float* __restrict__ t1,
                            const float* __restrict__ W,
                            float* __restrict__ out_use)
{
    int b  = blockIdx.x;
    int d4 = threadIdx.x;

    if (b >= 320) {                       // use copy
        int n = b - 320;
        ((float4*)(out_use + (size_t)n * DD))[d4] =
            ((const float4*)(t1 + (size_t)n * LL * DD))[d4];
        return;
    }
    int c  = b;
    int k4 = d4 * 4;
    __nv_bfloat16* Brow = g_B + (size_t)c * KT2;
    if (c >= OUTC) {
        uint2 z = make_uint2(0u, 0u);
        *(uint2*)(Brow + k4)       = z;
        *(uint2*)(Brow + 512 + k4) = z;
        return;
    }
    float4 wv = *(const float4*)(W + (size_t)c * DD + k4);
    __nv_bfloat16 h0 = __float2bfloat16(wv.x), h1 = __float2bfloat16(wv.y);
    __nv_bfloat16 h2 = __float2bfloat16(wv.z), h3 = __float2bfloat16(wv.w);
    __nv_bfloat16 l0 = __float2bfloat16(wv.x - __bfloat162float(h0));
    __nv_bfloat16 l1 = __float2bfloat16(wv.y - __bfloat162float(h1));
    __nv_bfloat16 l2 = __float2bfloat16(wv.z - __bfloat162float(h2));
    __nv_bfloat16 l3 = __float2bfloat16(wv.w - __bfloat162float(h3));
    __nv_bfloat16 hbuf[4] = {h0, h1, h2, h3};
    __nv_bfloat16 lbuf[4] = {l0, l1, l2, l3};
    *(uint2*)(Brow + k4)       = *(uint2*)hbuf;
    *(uint2*)(Brow + 512 + k4) = *(uint2*)lbuf;
}

// ---------------------------------------------------------------------------
// Kernel 2 (fused): means -> split-bf16 A (smem ring) + HMMA GEMM + LayerNorm.
// 127 CTAs x 512 threads (16 warps: 2 row-groups x 8 col-groups; 32x40/warp).
// Chunk-major schedule: chunk c -> stages (Ah*Bh, Al*Bh, Ah*Bl).
// smem: B ring 4x40KB (h0,h1 | l0,l1) + A ring 4x8KB (Ah0,Ah1,Al0,Al1).
// ---------------------------------------------------------------------------
#define B_SLOT 40960
#define A_SLOT 8192
#define A_BASE (4 * B_SLOT)                 // 163840
#define DYN_SMEM (4 * B_SLOT + 4 * A_SLOT)  // 196608

__global__ __launch_bounds__(512, 1)
void fused_kernel(const float* __restrict__ t1,
                  const int* __restrict__ ws32,
                  const float* __restrict__ blin,
                  const float* __restrict__ gamma,
                  const float* __restrict__ beta,
                  float* __restrict__ out)
{
    extern __shared__ __align__(1024) char dyns[];
    __shared__ float sBias[320], sGamma[320], sBeta[320];
    __shared__ float sRed[8][2][64];
    __shared__ float sMu[64], sInv[64];

    int t    = threadIdx.x;
    int w    = t >> 5;
    int lane = t & 31;
    int wr   = w & 1;        // rows 32*wr .. 32*wr+31
    int wc   = w >> 1;       // cols 40*wc .. 40*wc+39
    int ctaRow = blockIdx.x * 64;

    uint32_t dsm = smem_u32(dyns);

    for (int i = t; i < 320; i += 512) {
        sBias[i]  = (i < OUTC) ? blin[i]  : 0.f;
        sGamma[i] = (i < OUTC) ? gamma[i] : 0.f;
        sBeta[i]  = (i < OUTC) ? beta[i]  : 0.f;
    }

    // ---- B staging (cp.async): 5 x 16B per thread per slot ----
    const uint4* gB = (const uint4*)g_B;    // row stride 128 uint4
    auto issueB = [&](int part, int cc) {   // part 0=h,1=l
        uint32_t dst = dsm + part * 2 * B_SLOT + (cc & 1) * B_SLOT;
        int srcoff = (part ? 64 : 0) + cc * 8;
#pragma unroll
        for (int i = 0; i < 5; i++) {
            int idx = t + 512 * i;
            int row = idx >> 3, qq = idx & 7;
            uint32_t off = (uint32_t)(row * 128 + qq * 16);
            cp_async16(dst + (off ^ ((uint32_t)(row & 7) << 4)),
                       gB + (size_t)row * 128 + srcoff + qq);
        }
    };

    // ---- means task: thread -> (span r = t>>3, 16B slot q = t&7) ----
    int r_loc = t >> 3, qslot = t & 7;
    int gs = ctaRow + r_loc;
    int n  = gs / SS;
    bool is64 = (ws32[1] == 0 && ws32[3] == 0);
    long long start, end;
    if (is64) {
        const long long* ws64 = (const long long*)ws32;
        start = ws64[(size_t)gs * 2];
        end   = ws64[(size_t)gs * 2 + 1];
    } else {
        start = ws32[(size_t)gs * 2];
        end   = ws32[(size_t)gs * 2 + 1];
    }
    if (start > (long long)(LI_ - 1)) start = LI_ - 1;
    if (end   > (long long)LI_)       end   = LI_;
    int cnt = (int)(end - start);
    float invCnt = 1.0f / (float)cnt;
    const float* rowPtr =
        t1 + ((size_t)n * LL + 1 + (size_t)start) * DD + qslot * 8;
    bool fast = (cnt == 8);

    // A STS addresses (swizzled 16B slot)
    uint32_t aSwz = ((uint32_t)(r_loc * 128 + qslot * 16)) ^
                    ((uint32_t)(r_loc & 7) << 4);

    auto splitStoreA = [&](float4 sa, float4 sb, int cc) {
        float h[8];
        h[0] = __bfloat162float(__float2bfloat16(sa.x));
        h[1] = __bfloat162float(__float2bfloat16(sa.y));
        h[2] = __bfloat162float(__float2bfloat16(sa.z));
        h[3] = __bfloat162float(__float2bfloat16(sa.w));
        h[4] = __bfloat162float(__float2bfloat16(sb.x));
        h[5] = __bfloat162float(__float2bfloat16(sb.y));
        h[6] = __bfloat162float(__float2bfloat16(sb.z));
        h[7] = __bfloat162float(__float2bfloat16(sb.w));
        uint4 hi, lo;
        hi.x = pack_bf2(h[0], h[1]); hi.y = pack_bf2(h[2], h[3]);
        hi.z = pack_bf2(h[4], h[5]); hi.w = pack_bf2(h[6], h[7]);
        lo.x = pack_bf2(sa.x - h[0], sa.y - h[1]);
        lo.y = pack_bf2(sa.z - h[2], sa.w - h[3]);
        lo.z = pack_bf2(sb.x - h[4], sb.y - h[5]);
        lo.w = pack_bf2(sb.z - h[6], sb.w - h[7]);
        uint32_t hOff = A_BASE + (cc & 1) * A_SLOT;
        uint32_t lOff = hOff + 2 * A_SLOT;
        *(uint4*)(dyns + hOff + aSwz) = hi;
        *(uint4*)(dyns + lOff + aSwz) = lo;
    };

    // ---- prologue: B groups for chunk 0/1, A chunk 0 ----
    issueB(0, 0); CP_COMMIT();     // g1: Bh[0]
    issueB(1, 0); CP_COMMIT();     // g2: Bl[0]
    issueB(0, 1); CP_COMMIT();     // g3: Bh[1]

    {
        const float* p = rowPtr;   // chunk 0
        float4 s0 = make_float4(0.f, 0.f, 0.f, 0.f);
        float4 s1 = make_float4(0.f, 0.f, 0.f, 0.f);
        if (fast) {
            float4 v[16];
#pragma unroll
            for (int r2 = 0; r2 < 8; r2++) {
                v[2 * r2]     = *(const float4*)(p + (size_t)r2 * DD);
                v[2 * r2 + 1] = *(const float4*)(p + (size_t)r2 * DD + 4);
            }
#pragma unroll
            for (int r2 = 0; r2 < 8; r2++) {
                s0.x += v[2*r2].x; s0.y += v[2*r2].y; s0.z += v[2*r2].z; s0.w += v[2*r2].w;
                s1.x += v[2*r2+1].x; s1.y += v[2*r2+1].y; s1.z += v[2*r2+1].z; s1.w += v[2*r2+1].w;
            }
        } else {
            for (int r2 = 0; r2 < cnt; r2++) {
                float4 a = *(const float4*)(p + (size_t)r2 * DD);
                float4 b = *(const float4*)(p + (size_t)r2 * DD + 4);
                s0.x += a.x; s0.y += a.y; s0.z += a.z; s0.w += a.w;
                s1.x += b.x; s1.y += b.y; s1.z += b.z; s1.w += b.w;
            }
        }
        s0.x *= invCnt; s0.y *= invCnt; s0.z *= invCnt; s0.w *= invCnt;
        s1.x *= invCnt; s1.y *= invCnt; s1.z *= invCnt; s1.w *= invCnt;
        splitStoreA(s0, s1, 0);
    }

    // ---- GEMM accumulators & ldsm constants ----
    float acc[2][5][4];
#pragma unroll
    for (int mi = 0; mi < 2; mi++)
#pragma unroll
        for (int ni = 0; ni < 5; ni++)
#pragma unroll
            for (int r = 0; r < 4; r++) acc[mi][ni][r] = 0.f;

    uint32_t aoff0 = (uint32_t)((32 * wr + (lane & 15)) * 128);
    uint32_t aoff1 = (uint32_t)((32 * wr + (lane & 15) + 16) * 128);
    uint32_t axor  = (uint32_t)((lane & 7) << 4);
    uint32_t akl   = (uint32_t)(lane & 16);

    uint32_t boff0 = (uint32_t)((40 * wc + (lane & 7) + ((lane >> 4) & 1) * 8) * 128);
    uint32_t boff1 = boff0 + 16 * 128;
    uint32_t boff2 = (uint32_t)((40 * wc + 32 + (lane & 7)) * 128);
    uint32_t bxor  = (uint32_t)((lane & 7) << 4);
    uint32_t bkl   = (uint32_t)((lane & 8) * 2);

    auto mma_stage = [&](uint32_t aBase, uint32_t bBase) {
#pragma unroll
        for (int ks = 0; ks < 4; ++ks) {
            uint32_t a[2][4];
            uint32_t kA = (uint32_t)(ks * 32) + akl;
            ldsm_x4(aBase + aoff0 + (kA ^ axor), a[0][0], a[0][1], a[0][2], a[0][3]);
            ldsm_x4(aBase + aoff1 + (kA ^ axor), a[1][0], a[1][1], a[1][2], a[1][3]);

            uint32_t kB = (uint32_t)(ks * 32) + bkl;
            uint32_t b[10];
            ldsm_x4(bBase + boff0 + (kB ^ bxor), b[0], b[1], b[2], b[3]);
            ldsm_x4(bBase + boff1 + (kB ^ bxor), b[4], b[5], b[6], b[7]);
            ldsm_x2(bBase + boff2 + (kB ^ bxor), b[8], b[9]);
#pragma unroll
            for (int mi = 0; mi < 2; mi++) {
                mma16816(acc[mi][0], a[mi], b[0], b[1]);
                mma16816(acc[mi][1], a[mi], b[2], b[3]);
                mma16816(acc[mi][2], a[mi], b[4], b[5]);
                mma16816(acc[mi][3], a[mi], b[6], b[7]);
                mma16816(acc[mi][4], a[mi], b[8], b[9]);
            }
        }
    };

    // region offsets
    auto AH = [&](int c) { return dsm + A_BASE + (c & 1) * A_SLOT; };
    auto AL = [&](int c) { return dsm + A_BASE + 2 * A_SLOT + (c & 1) * A_SLOT; };
    auto BH = [&](int c) { return dsm + (c & 1) * B_SLOT; };
    auto BL = [&](int c) { return dsm + 2 * B_SLOT + (c & 1) * B_SLOT; };

    // ---- main loop: 8 chunks x 3 stages ----
#pragma unroll 1
    for (int c = 0; c < NCHK; ++c) {
        float4 v[16];
        const float* p = rowPtr + (c + 1) * 64;

        // ---------- stage k0: Ah[c] * Bh[c] ----------
        CP_WAIT2();
        __syncthreads();
        if (c + 1 < NCHK) issueB(1, c + 1);
        CP_COMMIT();
        mma_stage(AH(c), BH(c));

        // ---------- stage k1: Al[c] * Bh[c] ----------
        CP_COMMIT();                       // empty group (uniform count)
        if (c + 1 < NCHK && fast) {
#pragma unroll
            for (int r2 = 0; r2 < 4; r2++) {
                v[2 * r2]     = *(const float4*)(p + (size_t)r2 * DD);
                v[2 * r2 + 1] = *(const float4*)(p + (size_t)r2 * DD + 4);
            }
        }
        mma_stage(AL(c), BH(c));

        // ---------- stage k2: Ah[c] * Bl[c] ----------
        CP_WAIT2();
        __syncthreads();
        if (c + 2 < NCHK) issueB(0, c + 2);
        CP_COMMIT();

        float4 s0 = make_float4(0.f, 0.f, 0.f, 0.f);
        float4 s1 = make_float4(0.f, 0.f, 0.f, 0.f);
        if (c + 1 < NCHK) {
            if (fast) {
#pragma unroll
                for (int r2 = 0; r2 < 4; r2++) {
                    s0.x += v[2*r2].x; s0.y += v[2*r2].y; s0.z += v[2*r2].z; s0.w += v[2*r2].w;
                    s1.x += v[2*r2+1].x; s1.y += v[2*r2+1].y; s1.z += v[2*r2+1].z; s1.w += v[2*r2+1].w;
                }
#pragma unroll
                for (int r2 = 4; r2 < 8; r2++) {
                    v[2 * r2]     = *(const float4*)(p + (size_t)r2 * DD);
                    v[2 * r2 + 1] = *(const float4*)(p + (size_t)r2 * DD + 4);
                }
            } else {
                for (int r2 = 0; r2 < cnt; r2++) {
                    float4 a = *(const float4*)(p + (size_t)r2 * DD);
                    float4 b = *(const float4*)(p + (size_t)r2 * DD + 4);
                    s0.x += a.x; s0.y += a.y; s0.z += a.z; s0.w += a.w;
                    s1.x += b.x; s1.y += b.y; s1.z += b.z; s1.w += b.w;
                }
            }
        }

        mma_stage(AH(c), BL(c));

        if (c + 1 < NCHK) {
            if (fast) {
#pragma unroll
                for (int r2 = 4; r2 < 8; r2++) {
                    s0.x += v[2*r2].x; s0.y += v[2*r2].y; s0.z += v[2*r2].z; s0.w += v[2*r2].w;
                    s1.x += v[2*r2+1].x; s1.y += v[2*r2+1].y; s1.z += v[2*r2+1].z; s1.w += v[2*r2+1].w;
                }
            }
            s0.x *= invCnt; s0.y *= invCnt; s0.z *= invCnt; s0.w *= invCnt;
            s1.x *= invCnt; s1.y *= invCnt; s1.z *= invCnt; s1.w *= invCnt;
            splitStoreA(s0, s1, c + 1);
        }
    }

    // ---------------- epilogue: bias + LayerNorm ----------------
    int g = lane >> 2, q = lane & 3;

    float sum[4] = {0.f, 0.f, 0.f, 0.f};
    float sq[4]  = {0.f, 0.f, 0.f, 0.f};
#pragma unroll
    for (int mi = 0; mi < 2; mi++)
#pragma unroll
        for (int ni = 0; ni < 5; ni++) {
            int c0 = 40 * wc + 8 * ni + 2 * q;
            float b0 = sBias[c0], b1 = sBias[c0 + 1];
            float v0 = acc[mi][ni][0] + b0;
            float v1 = acc[mi][ni][1] + b1;
            float v2 = acc[mi][ni][2] + b0;
            float v3 = acc[mi][ni][3] + b1;
            acc[mi][ni][0] = v0; acc[mi][ni][1] = v1;
            acc[mi][ni][2] = v2; acc[mi][ni][3] = v3;
            sum[2 * mi]     += v0 + v1;  sq[2 * mi]     += v0 * v0 + v1 * v1;
            sum[2 * mi + 1] += v2 + v3;  sq[2 * mi + 1] += v2 * v2 + v3 * v3;
        }
#pragma unroll
    for (int off = 1; off <= 2; off <<= 1)
#pragma unroll
        for (int sl = 0; sl < 4; sl++) {
            sum[sl] += __shfl_xor_sync(0xffffffffu, sum[sl], off);
            sq[sl]  += __shfl_xor_sync(0xffffffffu, sq[sl],  off);
        }
    if (q == 0) {
#pragma unroll
        for (int sl = 0; sl < 4; sl++) {
            int lr = 32 * wr + 16 * (sl >> 1) + g + 8 * (sl & 1);
            sRed[wc][0][lr] = sum[sl];
            sRed[wc][1][lr] = sq[sl];
        }
    }
    __syncthreads();
    if (t < 64) {
        float S = 0.f, Q = 0.f;
#pragma unroll
        for (int k = 0; k < 8; k++) { S += sRed[k][0][t]; Q += sRed[k][1][t]; }
        float mu = S * (1.0f / OUTC);
        sMu[t]  = mu;
        sInv[t] = rsqrtf(Q * (1.0f / OUTC) - mu * mu + EPSF);
    }
    __syncthreads();

#pragma unroll
    for (int mi = 0; mi < 2; mi++) {
        int lr0 = 32 * wr + 16 * mi + g;
        int lr1 = lr0 + 8;
        float mu0 = sMu[lr0], in0 = sInv[lr0];
        float mu1 = sMu[lr1], in1 = sInv[lr1];
        float* o0 = out + (size_t)(ctaRow + lr0) * OUTC;
        float* o1 = out + (size_t)(ctaRow + lr1) * OUTC;
#pragma unroll
        for (int ni = 0; ni < 5; ni++) {
            int c0 = 40 * wc + 8 * ni + 2 * q;
            if (c0 < OUTC) {
                float ga = sGamma[c0], gb = sGamma[c0 + 1];
                float ba = sBeta[c0],  bb = sBeta[c0 + 1];
                float2 r0, r1;
                r0.x = (acc[mi][ni][0] - mu0) * in0 * ga + ba;
                r0.y = (acc[mi][ni][1] - mu0) * in0 * gb + bb;
                r1.x = (acc[mi][ni][2] - mu1) * in1 * ga + ba;
                r1.y = (acc[mi][ni][3] - mu1) * in1 * gb + bb;
                *(float2*)(o0 + c0) = r0;
                *(float2*)(o1 + c0) = r1;
            }
        }
    }
}

// ---------------------------------------------------------------------------
extern "C" void kernel_launch(void* const* d_in, const int* in_sizes, int n_in,
                              void* d_out, int out_size)
{
    const float* t1    = (const float*)d_in[0];
    const int*   ws    = (const int*)  d_in[1];
    const float* W     = (const float*)d_in[3];
    const float* blin  = (const float*)d_in[4];
    const float* gamma = (const float*)d_in[5];
    const float* beta  = (const float*)d_in[6];

    float* out = (float*)d_out;
    float* use = out + (size_t)NN * SS * OUTC;

    static bool attr_set = false;
    if (!attr_set) {
        cudaFuncSetAttribute(fused_kernel,
                             cudaFuncAttributeMaxDynamicSharedMemorySize, DYN_SMEM);
        attr_set = true;
    }

    prep_kernel<<<384, 128>>>(t1, W, use);
    fused_kernel<<<SS, 512, DYN_SMEM>>>(t1, ws, blin, gamma, beta, out);
}

// round 12
// speedup vs baseline: 1.2118x; 1.2118x over previous
#include <cuda_runtime.h>
#include <cuda_bf16.h>
#include <cstdint>

// Problem constants
#define NN   64
#define LL   1024
#define DD   512
#define LI_  1022
#define SS   127
#define OUTC 300
#define EPSF 1e-5f

#define KT2  1024          // dedup: [hi|lo]
#define NSTG 24            // 3 terms x 8 chunks
#define MR   8128          // NN*SS

// Global scratch (allocation-free rule)
__device__ __align__(128) __nv_bfloat16 g_A[(size_t)MR * KT2];   // [Ah|Al]
__device__ __align__(128) __nv_bfloat16 g_B[(size_t)320 * KT2];  // [Bh|Bl]

__device__ __forceinline__ uint32_t smem_u32(const void* p) {
    return (uint32_t)__cvta_generic_to_shared(p);
}
__device__ __forceinline__ void ldsm_x4(uint32_t addr, uint32_t& r0, uint32_t& r1,
                                        uint32_t& r2, uint32_t& r3) {
    asm volatile("ldmatrix.sync.aligned.m8n8.x4.shared.b16 {%0,%1,%2,%3}, [%4];"
                 : "=r"(r0), "=r"(r1), "=r"(r2), "=r"(r3) : "r"(addr));
}
__device__ __forceinline__ void ldsm_x2(uint32_t addr, uint32_t& r0, uint32_t& r1) {
    asm volatile("ldmatrix.sync.aligned.m8n8.x2.shared.b16 {%0,%1}, [%2];"
                 : "=r"(r0), "=r"(r1) : "r"(addr));
}
__device__ __forceinline__ void mma16816(float* c, const uint32_t* a,
                                         uint32_t b0, uint32_t b1) {
    asm volatile("mma.sync.aligned.m16n8k16.row.col.f32.bf16.bf16.f32 "
                 "{%0,%1,%2,%3}, {%4,%5,%6,%7}, {%8,%9}, {%0,%1,%2,%3};"
                 : "+f"(c[0]), "+f"(c[1]), "+f"(c[2]), "+f"(c[3])
                 : "r"(a[0]), "r"(a[1]), "r"(a[2]), "r"(a[3]), "r"(b0), "r"(b1));
}
__device__ __forceinline__ void cp_async16(uint32_t dst, const void* src) {
    asm volatile("cp.async.cg.shared.global [%0], [%1], 16;" :: "r"(dst), "l"(src));
}
#define CP_COMMIT() asm volatile("cp.async.commit_group;")
#define CP_WAIT2()  asm volatile("cp.async.wait_group 2;" ::: "memory")

// ---------------------------------------------------------------------------
// Kernel 1: fused  (a) span means -> split-bf16 g_A rows [Ah|Al] + `use` copy
//                  (b) W split    -> g_B rows [Bh|Bl]
// grid = 8448: blocks [0,8128) = means, [8128,8448) = W rows. 128 threads.
// ---------------------------------------------------------------------------
__global__ void prep_kernel(const float* __restrict__ t1,
                            const int* __restrict__ ws32,
                            const float* __restrict__ W,
                            float* __restrict__ out_use)
{
    int b  = blockIdx.x;
    int d4 = threadIdx.x;

    if (b >= MR) {                       // ---- W split path ----
        int c  = b - MR;
        int k4 = d4 * 4;
        __nv_bfloat16* Brow = g_B + (size_t)c * KT2;
        if (c >= OUTC) {
            uint2 z = make_uint2(0u, 0u);
            *(uint2*)(Brow + k4)       = z;
            *(uint2*)(Brow + 512 + k4) = z;
            return;
        }
        float4 wv = *(const float4*)(W + (size_t)c * DD + k4);
        __nv_bfloat16 h0 = __float2bfloat16(wv.x), h1 = __float2bfloat16(wv.y);
        __nv_bfloat16 h2 = __float2bfloat16(wv.z), h3 = __float2bfloat16(wv.w);
        __nv_bfloat16 l0 = __float2bfloat16(wv.x - __bfloat162float(h0));
        __nv_bfloat16 l1 = __float2bfloat16(wv.y - __bfloat162float(h1));
        __nv_bfloat16 l2 = __float2bfloat16(wv.z - __bfloat162float(h2));
        __nv_bfloat16 l3 = __float2bfloat16(wv.w - __bfloat162float(h3));
        __nv_bfloat16 hbuf[4] = {h0, h1, h2, h3};
        __nv_bfloat16 lbuf[4] = {l0, l1, l2, l3};
        *(uint2*)(Brow + k4)       = *(uint2*)hbuf;
        *(uint2*)(Brow + 512 + k4) = *(uint2*)lbuf;
        return;
    }

    // ---- means path ----
    __nv_bfloat16* Arow = g_A + (size_t)b * KT2;
    int n = b / SS;
    int s = b - n * SS;

    bool is64 = (ws32[1] == 0 && ws32[3] == 0);
    long long start, end;
    if (is64) {
        const long long* ws64 = (const long long*)ws32;
        start = ws64[(size_t)(n * SS + s) * 2];
        end   = ws64[(size_t)(n * SS + s) * 2 + 1];
    } else {
        start = ws32[(size_t)(n * SS + s) * 2];
        end   = ws32[(size_t)(n * SS + s) * 2 + 1];
    }
    if (start > (long long)(LI_ - 1)) start = LI_ - 1;
    if (end   > (long long)LI_)       end   = LI_;
    int cnt = (int)(end - start);

    const float4* base =
        (const float4*)(t1 + ((size_t)n * LL + 1 + (size_t)start) * DD) + d4;

    float4 acc = make_float4(0.f, 0.f, 0.f, 0.f);
    if (cnt == 8) {
        float4 v[8];
#pragma unroll
        for (int r = 0; r < 8; ++r) v[r] = base[(size_t)r * (DD / 4)];
#pragma unroll
        for (int r = 0; r < 8; ++r) {
            acc.x += v[r].x; acc.y += v[r].y; acc.z += v[r].z; acc.w += v[r].w;
        }
    } else {
        for (int r = 0; r < cnt; ++r) {
            float4 v = base[(size_t)r * (DD / 4)];
            acc.x += v.x; acc.y += v.y; acc.z += v.z; acc.w += v.w;
        }
    }
    float inv = 1.0f / (float)cnt;
    acc.x *= inv; acc.y *= inv; acc.z *= inv; acc.w *= inv;

    __nv_bfloat16 h0 = __float2bfloat16(acc.x), h1 = __float2bfloat16(acc.y);
    __nv_bfloat16 h2 = __float2bfloat16(acc.z), h3 = __float2bfloat16(acc.w);
    __nv_bfloat16 l0 = __float2bfloat16(acc.x - __bfloat162float(h0));
    __nv_bfloat16 l1 = __float2bfloat16(acc.y - __bfloat162float(h1));
    __nv_bfloat16 l2 = __float2bfloat16(acc.z - __bfloat162float(h2));
    __nv_bfloat16 l3 = __float2bfloat16(acc.w - __bfloat162float(h3));
    __nv_bfloat16 hbuf[4] = {h0, h1, h2, h3};
    __nv_bfloat16 lbuf[4] = {l0, l1, l2, l3};
    *(uint2*)(Arow + 4 * d4)       = *(uint2*)hbuf;   // Ah
    *(uint2*)(Arow + 512 + 4 * d4) = *(uint2*)lbuf;   // Al

    if (s == 0) {
        ((float4*)(out_use + (size_t)n * DD))[d4] =
            ((const float4*)(t1 + (size_t)n * LL * DD))[d4];
    }
}

// ---------------------------------------------------------------------------
// Kernel 2: HMMA GEMM (mma.sync m16n8k16 bf16) + fused LayerNorm.
// grid = 127 CTAs (64 rows), 512 threads (16 warps: 2 row x 8 col groups,
// warp tile 32x40). cp.async.cg 16B staging, 4-deep ring, 1 barrier/stage.
// Stage s: term=s>>3 selects (A seg, B seg): (h,h) (l,h) (h,l); chunk=s&7.
// ---------------------------------------------------------------------------
#define A_STG 8192                  // 64 rows * 128B
#define B_STG 40960                 // 320 rows * 128B
#define STG_BYTES (A_STG + B_STG)   // 49152
#define DYN_SMEM (4 * STG_BYTES)    // 196608

__global__ __launch_bounds__(512, 1)
void gemm_ln_kernel(const float* __restrict__ blin,
                    const float* __restrict__ gamma,
                    const float* __restrict__ beta,
                    float* __restrict__ out)
{
    extern __shared__ __align__(1024) char dyns[];
    __shared__ float sBias[320], sGamma[320], sBeta[320];
    __shared__ float sRed[8][2][64];
    __shared__ float sMu[64], sInv[64];

    int t    = threadIdx.x;
    int w    = t >> 5;
    int lane = t & 31;
    int wr   = w & 1;        // rows 32*wr .. 32*wr+31
    int wc   = w >> 1;       // cols 40*wc .. 40*wc+39
    int ctaRow = blockIdx.x * 64;

    for (int i = t; i < 320; i += 512) {
        sBias[i]  = (i < OUTC) ? blin[i]  : 0.f;
        sGamma[i] = (i < OUTC) ? gamma[i] : 0.f;
        sBeta[i]  = (i < OUTC) ? beta[i]  : 0.f;
    }

    float acc[2][5][4];
#pragma unroll
    for (int mi = 0; mi < 2; mi++)
#pragma unroll
        for (int ni = 0; ni < 5; ni++)
#pragma unroll
            for (int r = 0; r < 4; r++) acc[mi][ni][r] = 0.f;

    // ldmatrix per-thread constants
    uint32_t aoff0 = (uint32_t)((32 * wr + (lane & 15)) * 128);
    uint32_t aoff1 = aoff0 + 16 * 128;
    uint32_t axor  = (uint32_t)((lane & 7) << 4);
    uint32_t akl   = (uint32_t)(lane & 16);

    uint32_t boff0 = (uint32_t)((40 * wc + (lane & 7) + ((lane >> 4) & 1) * 8) * 128);
    uint32_t boff1 = boff0 + 16 * 128;
    uint32_t boff2 = (uint32_t)((40 * wc + 32 + (lane & 7)) * 128);
    uint32_t bxor  = (uint32_t)((lane & 7) << 4);
    uint32_t bkl   = (uint32_t)((lane & 8) * 2);

    // staging: per thread per stage: A 1 x 16B, B 5 x 16B (cp.async)
    const uint4* gA = (const uint4*)(g_A + (size_t)ctaRow * KT2);   // row stride 128 uint4
    const uint4* gB = (const uint4*)g_B;

    int arow_s = t >> 3, aq_s = t & 7;          // A: 512 items, 1/thread
    int brow_s[5], bq_s[5];                     // B: 2560 items, 5/thread
#pragma unroll
    for (int i = 0; i < 5; i++) {
        int idx = t + 512 * i;
        brow_s[i] = idx >> 3; bq_s[i] = idx & 7;
    }

    auto issue_stage = [&](int s) {
        int term = s >> 3, c = s & 7;
        int aK4 = (term == 1 ? 64 : 0) + c * 8;   // uint4 offset within row
        int bK4 = (term == 2 ? 64 : 0) + c * 8;
        int buf = s & 3;
        uint32_t a_s = smem_u32(dyns + buf * STG_BYTES);
        uint32_t b_s = a_s + A_STG;
        {
            uint32_t off = (uint32_t)(arow_s * 128 + aq_s * 16);
            cp_async16(a_s + (off ^ ((uint32_t)(arow_s & 7) << 4)),
                       gA + (size_t)arow_s * 128 + aK4 + aq_s);
        }
#pragma unroll
        for (int i = 0; i < 5; i++) {
            uint32_t off = (uint32_t)(brow_s[i] * 128 + bq_s[i] * 16);
            cp_async16(b_s + (off ^ ((uint32_t)(brow_s[i] & 7) << 4)),
                       gB + (size_t)brow_s[i] * 128 + bK4 + bq_s[i]);
        }
        CP_COMMIT();
    };

    // prologue: stages 0,1,2 in flight (3 groups)
    issue_stage(0);
    issue_stage(1);
    issue_stage(2);

    for (int s = 0; s < NSTG; ++s) {
        CP_WAIT2();              // stage s resident (pending <= 2)
        __syncthreads();         // all warps past compute(s-1); fill visible

        if (s + 3 < NSTG) issue_stage(s + 3);
        else              CP_COMMIT();      // keep group count telescoping

        int buf = s & 3;
        uint32_t aBase = smem_u32(dyns + buf * STG_BYTES);
        uint32_t bBase = aBase + A_STG;

#pragma unroll
        for (int ks = 0; ks < 4; ++ks) {
            uint32_t a[2][4];
            uint32_t kA = (uint32_t)(ks * 32) + akl;
            ldsm_x4(aBase + aoff0 + (kA ^ axor), a[0][0], a[0][1], a[0][2], a[0][3]);
            ldsm_x4(aBase + aoff1 + (kA ^ axor), a[1][0], a[1][1], a[1][2], a[1][3]);

            uint32_t kB = (uint32_t)(ks * 32) + bkl;
            uint32_t b[10];
            ldsm_x4(bBase + boff0 + (kB ^ bxor), b[0], b[1], b[2], b[3]);
            ldsm_x4(bBase + boff1 + (kB ^ bxor), b[4], b[5], b[6], b[7]);
            ldsm_x2(bBase + boff2 + (kB ^ bxor), b[8], b[9]);
#pragma unroll
            for (int mi = 0; mi < 2; mi++) {
                mma16816(acc[mi][0], a[mi], b[0], b[1]);
                mma16816(acc[mi][1], a[mi], b[2], b[3]);
                mma16816(acc[mi][2], a[mi], b[4], b[5]);
                mma16816(acc[mi][3], a[mi], b[6], b[7]);
                mma16816(acc[mi][4], a[mi], b[8], b[9]);
            }
        }
    }

    // ---------------- epilogue: bias + LayerNorm ----------------
    int g = lane >> 2, q = lane & 3;

    float sum[4] = {0.f, 0.f, 0.f, 0.f};
    float sq[4]  = {0.f, 0.f, 0.f, 0.f};
#pragma unroll
    for (int mi = 0; mi < 2; mi++)
#pragma unroll
        for (int ni = 0; ni < 5; ni++) {
            int c0 = 40 * wc + 8 * ni + 2 * q;
            float b0 = sBias[c0], b1 = sBias[c0 + 1];
            float v0 = acc[mi][ni][0] + b0;
            float v1 = acc[mi][ni][1] + b1;
            float v2 = acc[mi][ni][2] + b0;
            float v3 = acc[mi][ni][3] + b1;
            acc[mi][ni][0] = v0; acc[mi][ni][1] = v1;
            acc[mi][ni][2] = v2; acc[mi][ni][3] = v3;
            sum[2 * mi]     += v0 + v1;  sq[2 * mi]     += v0 * v0 + v1 * v1;
            sum[2 * mi + 1] += v2 + v3;  sq[2 * mi + 1] += v2 * v2 + v3 * v3;
        }
#pragma unroll
    for (int off = 1; off <= 2; off <<= 1)
#pragma unroll
        for (int sl = 0; sl < 4; sl++) {
            sum[sl] += __shfl_xor_sync(0xffffffffu, sum[sl], off);
            sq[sl]  += __shfl_xor_sync(0xffffffffu, sq[sl],  off);
        }
    if (q == 0) {
#pragma unroll
        for (int sl = 0; sl < 4; sl++) {
            int lr = 32 * wr + 16 * (sl >> 1) + g + 8 * (sl & 1);
            sRed[wc][0][lr] = sum[sl];
            sRed[wc][1][lr] = sq[sl];
        }
    }
    __syncthreads();
    if (t < 64) {
        float S = 0.f, Q = 0.f;
#pragma unroll
        for (int k = 0; k < 8; k++) { S += sRed[k][0][t]; Q += sRed[k][1][t]; }
        float mu = S * (1.0f / OUTC);
        sMu[t]  = mu;
        sInv[t] = rsqrtf(Q * (1.0f / OUTC) - mu * mu + EPSF);
    }
    __syncthreads();

#pragma unroll
    for (int mi = 0; mi < 2; mi++) {
        int lr0 = 32 * wr + 16 * mi + g;
        int lr1 = lr0 + 8;
        float mu0 = sMu[lr0], in0 = sInv[lr0];
        float mu1 = sMu[lr1], in1 = sInv[lr1];
        float* o0 = out + (size_t)(ctaRow + lr0) * OUTC;
        float* o1 = out + (size_t)(ctaRow + lr1) * OUTC;
#pragma unroll
        for (int ni = 0; ni < 5; ni++) {
            int c0 = 40 * wc + 8 * ni + 2 * q;
            if (c0 < OUTC) {
                float ga = sGamma[c0], gb = sGamma[c0 + 1];
                float ba = sBeta[c0],  bb = sBeta[c0 + 1];
                float2 r0, r1;
                r0.x = (acc[mi][ni][0] - mu0) * in0 * ga + ba;
                r0.y = (acc[mi][ni][1] - mu0) * in0 * gb + bb;
                r1.x = (acc[mi][ni][2] - mu1) * in1 * ga + ba;
                r1.y = (acc[mi][ni][3] - mu1) * in1 * gb + bb;
                *(float2*)(o0 + c0) = r0;
                *(float2*)(o1 + c0) = r1;
            }
        }
    }
}

// ---------------------------------------------------------------------------
extern "C" void kernel_launch(void* const* d_in, const int* in_sizes, int n_in,
                              void* d_out, int out_size)
{
    const float* t1    = (const float*)d_in[0];
    const int*   ws    = (const int*)  d_in[1];
    const float* W     = (const float*)d_in[3];
    const float* blin  = (const float*)d_in[4];
    const float* gamma = (const float*)d_in[5];
    const float* beta  = (const float*)d_in[6];

    float* out = (float*)d_out;
    float* use = out + (size_t)NN * SS * OUTC;

    static bool attr_set = false;
    if (!attr_set) {
        cudaFuncSetAttribute(gemm_ln_kernel,
                             cudaFuncAttributeMaxDynamicSharedMemorySize, DYN_SMEM);
        attr_set = true;
    }

    prep_kernel<<<MR + 320, 128>>>(t1, ws, W, use);
    gemm_ln_kernel<<<SS, 512, DYN_SMEM>>>(blin, gamma, beta, out);
}

// round 13
// speedup vs baseline: 1.2220x; 1.0084x over previous
#include <cuda_runtime.h>
#include <cuda_bf16.h>
#include <cstdint>

// Problem constants
#define NN   64
#define LL   1024
#define DD   512
#define LI_  1022
#define SS   127
#define OUTC 300
#define EPSF 1e-5f

#define KT2  1024          // dedup: [hi|lo]
#define NSTG 24            // 3 terms x 8 chunks
#define MR   8128          // NN*SS

// Global scratch (allocation-free rule)
__device__ __align__(128) __nv_bfloat16 g_A[(size_t)MR * KT2];   // [Ah|Al]
__device__ __align__(128) __nv_bfloat16 g_B[(size_t)320 * KT2];  // [Bh|Bl]

__device__ __forceinline__ uint32_t smem_u32(const void* p) {
    return (uint32_t)__cvta_generic_to_shared(p);
}
__device__ __forceinline__ void ldsm_x4(uint32_t addr, uint32_t& r0, uint32_t& r1,
                                        uint32_t& r2, uint32_t& r3) {
    asm volatile("ldmatrix.sync.aligned.m8n8.x4.shared.b16 {%0,%1,%2,%3}, [%4];"
                 : "=r"(r0), "=r"(r1), "=r"(r2), "=r"(r3) : "r"(addr));
}
__device__ __forceinline__ void ldsm_x2(uint32_t addr, uint32_t& r0, uint32_t& r1) {
    asm volatile("ldmatrix.sync.aligned.m8n8.x2.shared.b16 {%0,%1}, [%2];"
                 : "=r"(r0), "=r"(r1) : "r"(addr));
}
__device__ __forceinline__ void mma16816(float* c, const uint32_t* a,
                                         uint32_t b0, uint32_t b1) {
    asm volatile("mma.sync.aligned.m16n8k16.row.col.f32.bf16.bf16.f32 "
                 "{%0,%1,%2,%3}, {%4,%5,%6,%7}, {%8,%9}, {%0,%1,%2,%3};"
                 : "+f"(c[0]), "+f"(c[1]), "+f"(c[2]), "+f"(c[3])
                 : "r"(a[0]), "r"(a[1]), "r"(a[2]), "r"(a[3]), "r"(b0), "r"(b1));
}
__device__ __forceinline__ void cp_async16(uint32_t dst, const void* src) {
    asm volatile("cp.async.cg.shared.global [%0], [%1], 16;" :: "r"(dst), "l"(src));
}
__device__ __forceinline__ void cp_async_arrive_noinc(uint32_t mbar) {
    asm volatile("cp.async.mbarrier.arrive.noinc.shared.b64 [%0];"
                 :: "r"(mbar) : "memory");
}
__device__ __forceinline__ void mbar_init(uint32_t mbar, uint32_t cnt) {
    asm volatile("mbarrier.init.shared.b64 [%0], %1;" :: "r"(mbar), "r"(cnt) : "memory");
}
__device__ __forceinline__ void mbar_arrive(uint32_t mbar) {
    asm volatile("mbarrier.arrive.shared.b64 _, [%0];" :: "r"(mbar) : "memory");
}
__device__ __forceinline__ void mbar_wait(uint32_t mbar, uint32_t parity) {
    uint32_t done;
    asm volatile("{\n\t.reg .pred p;\n\t"
                 "mbarrier.try_wait.parity.acquire.cta.shared::cta.b64 p, [%1], %2;\n\t"
                 "selp.b32 %0, 1, 0, p;\n\t}"
                 : "=r"(done) : "r"(mbar), "r"(parity) : "memory");
    if (!done) {
        asm volatile("{\n\t.reg .pred P1;\n\t"
                     "WL_%=:\n\t"
                     "mbarrier.try_wait.parity.acquire.cta.shared::cta.b64 P1, [%0], %1, 0x989680;\n\t"
                     "@P1 bra.uni WD_%=;\n\t"
                     "bra.uni WL_%=;\n\t"
                     "WD_%=:\n\t}"
                     :: "r"(mbar), "r"(parity) : "memory");
    }
}

// ---------------------------------------------------------------------------
// Kernel 1: fused  (a) span means -> split-bf16 g_A rows [Ah|Al] + `use` copy
//                  (b) W split    -> g_B rows [Bh|Bl]
// grid = 8448: blocks [0,8128) = means, [8128,8448) = W rows. 128 threads.
// ---------------------------------------------------------------------------
__global__ void prep_kernel(const float* __restrict__ t1,
                            const int* __restrict__ ws32,
                            const float* __restrict__ W,
                            float* __restrict__ out_use)
{
    int b  = blockIdx.x;
    int d4 = threadIdx.x;

    if (b >= MR) {                       // ---- W split path ----
        int c  = b - MR;
        int k4 = d4 * 4;
        __nv_bfloat16* Brow = g_B + (size_t)c * KT2;
        if (c >= OUTC) {
            uint2 z = make_uint2(0u, 0u);
            *(uint2*)(Brow + k4)       = z;
            *(uint2*)(Brow + 512 + k4) = z;
            return;
        }
        float4 wv = *(const float4*)(W + (size_t)c * DD + k4);
        __nv_bfloat16 h0 = __float2bfloat16(wv.x), h1 = __float2bfloat16(wv.y);
        __nv_bfloat16 h2 = __float2bfloat16(wv.z), h3 = __float2bfloat16(wv.w);
        __nv_bfloat16 l0 = __float2bfloat16(wv.x - __bfloat162float(h0));
        __nv_bfloat16 l1 = __float2bfloat16(wv.y - __bfloat162float(h1));
        __nv_bfloat16 l2 = __float2bfloat16(wv.z - __bfloat162float(h2));
        __nv_bfloat16 l3 = __float2bfloat16(wv.w - __bfloat162float(h3));
        __nv_bfloat16 hbuf[4] = {h0, h1, h2, h3};
        __nv_bfloat16 lbuf[4] = {l0, l1, l2, l3};
        *(uint2*)(Brow + k4)       = *(uint2*)hbuf;
        *(uint2*)(Brow + 512 + k4) = *(uint2*)lbuf;
        return;
    }

    // ---- means path ----
    __nv_bfloat16* Arow = g_A + (size_t)b * KT2;
    int n = b / SS;
    int s = b - n * SS;

    bool is64 = (ws32[1] == 0 && ws32[3] == 0);
    long long start, end;
    if (is64) {
        const long long* ws64 = (const long long*)ws32;
        start = ws64[(size_t)(n * SS + s) * 2];
        end   = ws64[(size_t)(n * SS + s) * 2 + 1];
    } else {
        start = ws32[(size_t)(n * SS + s) * 2];
        end   = ws32[(size_t)(n * SS + s) * 2 + 1];
    }
    if (start > (long long)(LI_ - 1)) start = LI_ - 1;
    if (end   > (long long)LI_)       end   = LI_;
    int cnt = (int)(end - start);

    const float4* base =
        (const float4*)(t1 + ((size_t)n * LL + 1 + (size_t)start) * DD) + d4;

    float4 acc = make_float4(0.f, 0.f, 0.f, 0.f);
    if (cnt == 8) {
        float4 v[8];
#pragma unroll
        for (int r = 0; r < 8; ++r) v[r] = base[(size_t)r * (DD / 4)];
#pragma unroll
        for (int r = 0; r < 8; ++r) {
            acc.x += v[r].x; acc.y += v[r].y; acc.z += v[r].z; acc.w += v[r].w;
        }
    } else {
        for (int r = 0; r < cnt; ++r) {
            float4 v = base[(size_t)r * (DD / 4)];
            acc.x += v.x; acc.y += v.y; acc.z += v.z; acc.w += v.w;
        }
    }
    float inv = 1.0f / (float)cnt;
    acc.x *= inv; acc.y *= inv; acc.z *= inv; acc.w *= inv;

    __nv_bfloat16 h0 = __float2bfloat16(acc.x), h1 = __float2bfloat16(acc.y);
    __nv_bfloat16 h2 = __float2bfloat16(acc.z), h3 = __float2bfloat16(acc.w);
    __nv_bfloat16 l0 = __float2bfloat16(acc.x - __bfloat162float(h0));
    __nv_bfloat16 l1 = __float2bfloat16(acc.y - __bfloat162float(h1));
    __nv_bfloat16 l2 = __float2bfloat16(acc.z - __bfloat162float(h2));
    __nv_bfloat16 l3 = __float2bfloat16(acc.w - __bfloat162float(h3));
    __nv_bfloat16 hbuf[4] = {h0, h1, h2, h3};
    __nv_bfloat16 lbuf[4] = {l0, l1, l2, l3};
    *(uint2*)(Arow + 4 * d4)       = *(uint2*)hbuf;   // Ah
    *(uint2*)(Arow + 512 + 4 * d4) = *(uint2*)lbuf;   // Al

    if (s == 0) {
        ((float4*)(out_use + (size_t)n * DD))[d4] =
            ((const float4*)(t1 + (size_t)n * LL * DD))[d4];
    }
}

// ---------------------------------------------------------------------------
// Kernel 2: warp-specialized HMMA GEMM + fused LayerNorm.
// 576 threads: warps 0-15 consumers (2 row x 8 col groups, 32x40/warp),
// warps 16-17 producers (cp.async all staging, mbarrier-signaled, 4-slot ring).
// NO __syncthreads in the mainloop.
// ---------------------------------------------------------------------------
#define A_STG 8192                  // 64 rows * 128B
#define B_STG 40960                 // 320 rows * 128B
#define STG_BYTES (A_STG + B_STG)   // 49152
#define DYN_SMEM (4 * STG_BYTES)    // 196608
#define NPROD 64                    // producer threads (warps 16,17)

__global__ __launch_bounds__(576, 1)
void gemm_ln_kernel(const float* __restrict__ blin,
                    const float* __restrict__ gamma,
                    const float* __restrict__ beta,
                    float* __restrict__ out)
{
    extern __shared__ __align__(1024) char dyns[];
    __shared__ __align__(8) uint64_t mbFull[4], mbEmpty[4];
    __shared__ float sBias[320], sGamma[320], sBeta[320];
    __shared__ float sRed[8][2][64];
    __shared__ float sMu[64], sInv[64];

    int t    = threadIdx.x;
    int w    = t >> 5;
    int lane = t & 31;
    int ctaRow = blockIdx.x * 64;

    uint32_t dsm = smem_u32(dyns);
    uint32_t fullA = smem_u32(&mbFull[0]);
    uint32_t emptyA = smem_u32(&mbEmpty[0]);

    for (int i = t; i < 320; i += 576) {
        sBias[i]  = (i < OUTC) ? blin[i]  : 0.f;
        sGamma[i] = (i < OUTC) ? gamma[i] : 0.f;
        sBeta[i]  = (i < OUTC) ? beta[i]  : 0.f;
    }
    if (t == 0) {
#pragma unroll
        for (int i = 0; i < 4; i++) {
            mbar_init(fullA + 8 * i, NPROD);   // one arrive per producer thread
            mbar_init(emptyA + 8 * i, 16);     // one arrive per consumer warp
        }
    }
    __syncthreads();

    const uint4* gA = (const uint4*)(g_A + (size_t)ctaRow * KT2);   // row stride 128 u4
    const uint4* gB = (const uint4*)g_B;

    if (w >= 16) {
        // =================== PRODUCER (warps 16,17) ===================
        int pt = t - 512;                       // 0..63
#pragma unroll 1
        for (int s = 0; s < NSTG; ++s) {
            int buf = s & 3, wrap = s >> 2;
            if (wrap > 0) mbar_wait(emptyA + 8 * buf, (uint32_t)((wrap - 1) & 1));
            int term = s >> 3, c = s & 7;
            int aK4 = (term == 1 ? 64 : 0) + c * 8;
            int bK4 = (term == 2 ? 64 : 0) + c * 8;
            uint32_t a_s = dsm + (uint32_t)buf * STG_BYTES;
            uint32_t b_s = a_s + A_STG;
            // A: 512 items (row,q), 8 per thread
#pragma unroll
            for (int i = 0; i < 8; i++) {
                int j = pt + NPROD * i;
                int row = j >> 3, q = j & 7;
                uint32_t off = (uint32_t)(row * 128 + q * 16);
                cp_async16(a_s + (off ^ ((uint32_t)(row & 7) << 4)),
                           gA + (size_t)row * 128 + aK4 + q);
            }
            // B: 2560 items, 40 per thread
#pragma unroll
            for (int i = 0; i < 40; i++) {
                int j = pt + NPROD * i;
                int row = j >> 3, q = j & 7;
                uint32_t off = (uint32_t)(row * 128 + q * 16);
                cp_async16(b_s + (off ^ ((uint32_t)(row & 7) << 4)),
                           gB + (size_t)row * 128 + bK4 + q);
            }
            cp_async_arrive_noinc(fullA + 8 * buf);
        }
    } else {
        // =================== CONSUMERS (warps 0-15) ===================
        int wr = w & 1;        // rows 32*wr .. 32*wr+31
        int wc = w >> 1;       // cols 40*wc .. 40*wc+39

        float acc[2][5][4];
#pragma unroll
        for (int mi = 0; mi < 2; mi++)
#pragma unroll
            for (int ni = 0; ni < 5; ni++)
#pragma unroll
                for (int r = 0; r < 4; r++) acc[mi][ni][r] = 0.f;

        uint32_t aoff0 = (uint32_t)((32 * wr + (lane & 15)) * 128);
        uint32_t aoff1 = aoff0 + 16 * 128;
        uint32_t axor  = (uint32_t)((lane & 7) << 4);
        uint32_t akl   = (uint32_t)(lane & 16);

        uint32_t boff0 = (uint32_t)((40 * wc + (lane & 7) + ((lane >> 4) & 1) * 8) * 128);
        uint32_t boff1 = boff0 + 16 * 128;
        uint32_t boff2 = (uint32_t)((40 * wc + 32 + (lane & 7)) * 128);
        uint32_t bxor  = (uint32_t)((lane & 7) << 4);
        uint32_t bkl   = (uint32_t)((lane & 8) * 2);

#pragma unroll 1
        for (int s = 0; s < NSTG; ++s) {
            int buf = s & 3;
            mbar_wait(fullA + 8 * buf, (uint32_t)((s >> 2) & 1));

            uint32_t aBase = dsm + (uint32_t)buf * STG_BYTES;
            uint32_t bBase = aBase + A_STG;

#pragma unroll
            for (int ks = 0; ks < 4; ++ks) {
                uint32_t a[2][4];
                uint32_t kA = (uint32_t)(ks * 32) + akl;
                ldsm_x4(aBase + aoff0 + (kA ^ axor), a[0][0], a[0][1], a[0][2], a[0][3]);
                ldsm_x4(aBase + aoff1 + (kA ^ axor), a[1][0], a[1][1], a[1][2], a[1][3]);

                uint32_t kB = (uint32_t)(ks * 32) + bkl;
                uint32_t b[10];
                ldsm_x4(bBase + boff0 + (kB ^ bxor), b[0], b[1], b[2], b[3]);
                ldsm_x4(bBase + boff1 + (kB ^ bxor), b[4], b[5], b[6], b[7]);
                ldsm_x2(bBase + boff2 + (kB ^ bxor), b[8], b[9]);
#pragma unroll
                for (int mi = 0; mi < 2; mi++) {
                    mma16816(acc[mi][0], a[mi], b[0], b[1]);
                    mma16816(acc[mi][1], a[mi], b[2], b[3]);
                    mma16816(acc[mi][2], a[mi], b[4], b[5]);
                    mma16816(acc[mi][3], a[mi], b[6], b[7]);
                    mma16816(acc[mi][4], a[mi], b[8], b[9]);
                }
            }
            __syncwarp();
            if (lane == 0) mbar_arrive(emptyA + 8 * buf);
        }

        // ---------------- epilogue part 1: partial sums ----------------
        int g = lane >> 2, q = lane & 3;
        float sum[4] = {0.f, 0.f, 0.f, 0.f};
        float sq[4]  = {0.f, 0.f, 0.f, 0.f};
#pragma unroll
        for (int mi = 0; mi < 2; mi++)
#pragma unroll
            for (int ni = 0; ni < 5; ni++) {
                int c0 = 40 * wc + 8 * ni + 2 * q;
                float b0 = sBias[c0], b1 = sBias[c0 + 1];
                float v0 = acc[mi][ni][0] + b0;
                float v1 = acc[mi][ni][1] + b1;
                float v2 = acc[mi][ni][2] + b0;
                float v3 = acc[mi][ni][3] + b1;
                acc[mi][ni][0] = v0; acc[mi][ni][1] = v1;
                acc[mi][ni][2] = v2; acc[mi][ni][3] = v3;
                sum[2 * mi]     += v0 + v1;  sq[2 * mi]     += v0 * v0 + v1 * v1;
                sum[2 * mi + 1] += v2 + v3;  sq[2 * mi + 1] += v2 * v2 + v3 * v3;
            }
#pragma unroll
        for (int off = 1; off <= 2; off <<= 1)
#pragma unroll
            for (int sl = 0; sl < 4; sl++) {
                sum[sl] += __shfl_xor_sync(0xffffffffu, sum[sl], off);
                sq[sl]  += __shfl_xor_sync(0xffffffffu, sq[sl],  off);
            }
        if (q == 0) {
#pragma unroll
            for (int sl = 0; sl < 4; sl++) {
                int lr = 32 * wr + 16 * (sl >> 1) + g + 8 * (sl & 1);
                sRed[wc][0][lr] = sum[sl];
                sRed[wc][1][lr] = sq[sl];
            }
        }

        // stash per-thread state for part 2 (kept in regs; fall through)
        __syncthreads();    // consumers + producer all arrive (producer below)
        if (t < 64) {
            float S = 0.f, Q = 0.f;
#pragma unroll
            for (int k = 0; k < 8; k++) { S += sRed[k][0][t]; Q += sRed[k][1][t]; }
            float mu = S * (1.0f / OUTC);
            sMu[t]  = mu;
            sInv[t] = rsqrtf(Q * (1.0f / OUTC) - mu * mu + EPSF);
        }
        __syncthreads();

#pragma unroll
        for (int mi = 0; mi < 2; mi++) {
            int lr0 = 32 * wr + 16 * mi + g;
            int lr1 = lr0 + 8;
            float mu0 = sMu[lr0], in0 = sInv[lr0];
            float mu1 = sMu[lr1], in1 = sInv[lr1];
            float* o0 = out + (size_t)(ctaRow + lr0) * OUTC;
            float* o1 = out + (size_t)(ctaRow + lr1) * OUTC;
#pragma unroll
            for (int ni = 0; ni < 5; ni++) {
                int c0 = 40 * wc + 8 * ni + 2 * q;
                if (c0 < OUTC) {
                    float ga = sGamma[c0], gb = sGamma[c0 + 1];
                    float ba = sBeta[c0],  bb = sBeta[c0 + 1];
                    float2 r0, r1;
                    r0.x = (acc[mi][ni][0] - mu0) * in0 * ga + ba;
                    r0.y = (acc[mi][ni][1] - mu0) * in0 * gb + bb;
                    r1.x = (acc[mi][ni][2] - mu1) * in1 * ga + ba;
                    r1.y = (acc[mi][ni][3] - mu1) * in1 * gb + bb;
                    *(float2*)(o0 + c0) = r0;
                    *(float2*)(o1 + c0) = r1;
                }
            }
        }
        return;
    }

    // producer path joins the two epilogue barriers, does no epilogue work
    __syncthreads();
    __syncthreads();
}

// ---------------------------------------------------------------------------
extern "C" void kernel_launch(void* const* d_in, const int* in_sizes, int n_in,
                              void* d_out, int out_size)
{
    const float* t1    = (const float*)d_in[0];
    const int*   ws    = (const int*)  d_in[1];
    const float* W     = (const float*)d_in[3];
    const float* blin  = (const float*)d_in[4];
    const float* gamma = (const float*)d_in[5];
    const float* beta  = (const float*)d_in[6];

    float* out = (float*)d_out;
    float* use = out + (size_t)NN * SS * OUTC;

    static bool attr_set = false;
    if (!attr_set) {
        cudaFuncSetAttribute(gemm_ln_kernel,
                             cudaFuncAttributeMaxDynamicSharedMemorySize, DYN_SMEM);
        attr_set = true;
    }

    prep_kernel<<<MR + 320, 128>>>(t1, ws, W, use);
    gemm_ln_kernel<<<SS, 576, DYN_SMEM>>>(blin, gamma, beta, out);
}